// round 14
// baseline (speedup 1.0000x reference)
#include <cuda_runtime.h>
#include <cuda_fp16.h>
#include <cstdint>

#define NN 12288
#define DD 128
#define JSPLIT 3
#define JLEN (NN / JSPLIT)      // 4096
#define KC 32
#define NC (JLEN / KC)          // 128 chunks
#define MB 128
#define MBLK (NN / MB)          // 96

// dynamic smem layout
#define SPH_BYTES  (2 * 128 * 40 * 2)     // 20480 (buf stride 10240)
#define SVH_BYTES  (2 * 128 * 40 * 2)
#define SPH_OFF    0
#define SVH_OFF    SPH_BYTES
#define DEN_OFF    (SPH_BYTES + SVH_BYTES)
#define SMEM_BYTES (DEN_OFF + 128 * 4)    // 41472
#define BUF_STRIDE 10240                   // 128*40*2 bytes

// ---------------- static scratch ----------------
__device__ float  g_WT[DD * DD];
__device__ float  g_V [(size_t)NN * DD];
__device__ __half g_VhT[(size_t)DD * NN];          // fp16 V transposed: [dim][node]
__device__ float  g_s[NN], g_t[NN];
__device__ float  g_Es[NN], g_Et[NN], g_Fs[NN], g_Ft[NN];
__device__ float  g_parts[JSPLIT][(size_t)NN * DD];
__device__ float  g_dparts[JSPLIT][NN];

__device__ __forceinline__ void mma_f16_16x8x16(float* c, const uint32_t* a,
                                                uint32_t b0, uint32_t b1) {
    asm volatile(
        "mma.sync.aligned.m16n8k16.row.col.f32.f16.f16.f32 "
        "{%0,%1,%2,%3}, {%4,%5,%6,%7}, {%8,%9}, {%0,%1,%2,%3};"
        : "+f"(c[0]), "+f"(c[1]), "+f"(c[2]), "+f"(c[3])
        : "r"(a[0]), "r"(a[1]), "r"(a[2]), "r"(a[3]), "r"(b0), "r"(b1));
}
__device__ __forceinline__ void ldm_x4(uint32_t* r, uint32_t addr) {
    asm volatile("ldmatrix.sync.aligned.m8n8.x4.shared.b16 {%0,%1,%2,%3}, [%4];"
                 : "=r"(r[0]), "=r"(r[1]), "=r"(r[2]), "=r"(r[3]) : "r"(addr));
}
__device__ __forceinline__ void ldm_x2(uint32_t& r0, uint32_t& r1, uint32_t addr) {
    asm volatile("ldmatrix.sync.aligned.m8n8.x2.shared.b16 {%0,%1}, [%2];"
                 : "=r"(r0), "=r"(r1) : "r"(addr));
}
__device__ __forceinline__ void cp_async16(uint32_t dst, const void* src) {
    asm volatile("cp.async.ca.shared.global [%0], [%1], 16;"
                 :: "r"(dst), "l"(src) : "memory");
}
__device__ __forceinline__ void cp_commit() {
    asm volatile("cp.async.commit_group;" ::: "memory");
}
__device__ __forceinline__ void cp_wait0() {
    asm volatile("cp.async.wait_group 0;" ::: "memory");
}
__device__ __forceinline__ void pf_l1(const void* p) {
    asm volatile("prefetch.global.L1 [%0];" :: "l"(p));
}
__device__ __forceinline__ uint32_t h2u(float lo, float hi) {
    __half2 h = __float22half2_rn(make_float2(lo, hi));
    return *(uint32_t*)&h;
}

// ---------------- Kernel A0: transpose W ----------------
__global__ void k_transW(const float* __restrict__ W) {
    int i = blockIdx.x * 256 + threadIdx.x;
    if (i < DD * DD) {
        int d = i >> 7, k = i & 127;
        g_WT[k * DD + d] = W[i];
    }
}

// ---------------- Kernel A: e_new = emb @ W^T ----------------
__global__ __launch_bounds__(256) void k_enew(const float* __restrict__ emb) {
    const int rb = blockIdx.x * 16;
    const int tid = threadIdx.x;
    __shared__ float es[16][128];
    for (int i = tid; i < 16 * 128; i += 256) {
        int r = i >> 7, k = i & 127;
        es[r][k] = emb[(size_t)(rb + r) * DD + k];
    }
    __syncthreads();
    const int rg = tid >> 5;
    const int dq = tid & 31;
    float acc[2][4];
    #pragma unroll
    for (int i = 0; i < 2; i++)
        #pragma unroll
        for (int j = 0; j < 4; j++) acc[i][j] = 0.f;
    #pragma unroll 4
    for (int k = 0; k < 128; ++k) {
        float4 wv = *(const float4*)&g_WT[k * DD + 4 * dq];
        float e0 = es[rg * 2 + 0][k];
        float e1 = es[rg * 2 + 1][k];
        acc[0][0] += e0 * wv.x; acc[0][1] += e0 * wv.y; acc[0][2] += e0 * wv.z; acc[0][3] += e0 * wv.w;
        acc[1][0] += e1 * wv.x; acc[1][1] += e1 * wv.y; acc[1][2] += e1 * wv.z; acc[1][3] += e1 * wv.w;
    }
    #pragma unroll
    for (int rr = 0; rr < 2; ++rr) {
        size_t row = (size_t)(rb + rg * 2 + rr) * DD;
        *(float4*)&g_V[row + 4 * dq] = make_float4(acc[rr][0], acc[rr][1], acc[rr][2], acc[rr][3]);
    }
}

// ---------------- Kernel A2: transpose V -> fp16 [dim][node] ----------------
__global__ void k_vhT() {
    __shared__ float tile[32][33];
    int nb = blockIdx.x * 32, db = blockIdx.y * 32;
    int tx = threadIdx.x, ty = threadIdx.y;   // 32x8
    #pragma unroll
    for (int i = 0; i < 32; i += 8)
        tile[ty + i][tx] = g_V[(size_t)(nb + ty + i) * DD + db + tx];
    __syncthreads();
    #pragma unroll
    for (int i = 0; i < 32; i += 8)
        g_VhT[(size_t)(db + ty + i) * NN + nb + tx] = __float2half(tile[tx][ty + i]);
}

// ---------------- Kernel B: per-row scalars ----------------
__global__ void k_scal(const float* __restrict__ a) {
    const int i = blockIdx.x;
    const int tid = threadIdx.x;  // 128
    float v = g_V[(size_t)i * DD + tid];
    float sp = v * a[tid];
    float tp = v * a[DD + tid];
    #pragma unroll
    for (int off = 16; off; off >>= 1) {
        sp += __shfl_down_sync(0xffffffffu, sp, off);
        tp += __shfl_down_sync(0xffffffffu, tp, off);
    }
    __shared__ float rs[4], rt[4];
    int w = tid >> 5;
    if ((tid & 31) == 0) { rs[w] = sp; rt[w] = tp; }
    __syncthreads();
    if (tid == 0) {
        float s = rs[0] + rs[1] + rs[2] + rs[3];
        float t = rt[0] + rt[1] + rt[2] + rt[3];
        g_s[i] = s; g_Es[i] = expf(s); g_Fs[i] = expf(0.01f * s);
        g_t[i] = t; g_Et[i] = expf(t); g_Ft[i] = expf(0.01f * t);
    }
}

// ---------------- Kernel C: pipelined fp16 mma.sync + ldmatrix ----------------
__global__ __launch_bounds__(256, 2) void k_mma(const int* __restrict__ adj) {
    extern __shared__ char smemc[];
    __half (*sPh)[128][40] = (__half (*)[128][40])(smemc + SPH_OFF);
    float* sDen            = (float*)(smemc + DEN_OFF);
    const uint32_t sph_base = (uint32_t)__cvta_generic_to_shared(smemc + SPH_OFF);
    const uint32_t svh_base = (uint32_t)__cvta_generic_to_shared(smemc + SVH_OFF);

    const int tid = threadIdx.x;
    const int w   = tid >> 5;
    const int l   = tid & 31;
    const int g   = l >> 2;
    const int t4  = l & 3;
    const int rb  = blockIdx.x * MB;
    const int jsp = blockIdx.y;

    const int mrow = (w & 3) * 32;
    const int ncol = (w >> 2) * 64;

    const int r = tid >> 1;
    const int h = tid & 1;
    const float rowEs = g_Es[rb + r];
    const float rowFs = g_Fs[rb + r];
    const size_t adjrow = (size_t)(rb + r) * NN;

    // ldmatrix per-lane base addresses (byte offsets, buf 0)
    const int la   = l & 7;
    const int lb8  = (l >> 3) & 1;
    const int lc16 = (l >> 4) & 1;
    uint32_t aAddr[2];
    #pragma unroll
    for (int m = 0; m < 2; ++m)
        aAddr[m] = sph_base +
            (uint32_t)(((mrow + 16 * m + la + 8 * lb8) * 40 + 8 * lc16) * 2);
    const uint32_t bAddr = svh_base +
        (uint32_t)(((ncol + la) * 40 + 8 * lb8) * 2);

    float denreg = 0.f;

    float acc[2][8][4];
    #pragma unroll
    for (int m = 0; m < 2; m++)
        #pragma unroll
        for (int n = 0; n < 8; n++)
            #pragma unroll
            for (int i = 0; i < 4; i++) acc[m][n][i] = 0.f;

    const int jbase = jsp * JLEN;

    #define STAGE_V(jb_, buf_)                                                    \
        {                                                                         \
            _Pragma("unroll")                                                     \
            for (int it = 0; it < 2; ++it) {                                      \
                int f_ = tid + it * 256;                                          \
                int d_ = f_ >> 2, q_ = f_ & 3;                                    \
                uint32_t dst_ = svh_base +                                        \
                    (uint32_t)(((buf_) * 128 * 40 + d_ * 40 + 8 * q_) * 2);       \
                cp_async16(dst_, g_VhT + (size_t)d_ * NN + (jb_) + 8 * q_);       \
            }                                                                     \
            cp_commit();                                                          \
        }

    // build 16 cols [16h,16h+16) of row r; sign(s+t) via Es*Et >= 1 (no g_t)
    #define BUILD_P(jb_, A4_, pb_)                                                \
        {                                                                         \
            float p_[16];                                                         \
            float psum_ = 0.f;                                                    \
            _Pragma("unroll")                                                     \
            for (int q_ = 0; q_ < 4; ++q_) {                                      \
                const int j_ = (jb_) + 16 * h + 4 * q_;                           \
                int4   av  = A4_[q_];                                             \
                float4 etv = *(const float4*)(g_Et + j_);                         \
                float4 ftv = *(const float4*)(g_Ft + j_);                         \
                float x_, y_;                                                     \
                x_ = rowEs * etv.x; y_ = rowFs * ftv.x;                           \
                p_[4*q_+0] = (av.x > 0) ? ((x_ >= 1.f) ? x_ : y_) : 0.f;          \
                x_ = rowEs * etv.y; y_ = rowFs * ftv.y;                           \
                p_[4*q_+1] = (av.y > 0) ? ((x_ >= 1.f) ? x_ : y_) : 0.f;          \
                x_ = rowEs * etv.z; y_ = rowFs * ftv.z;                           \
                p_[4*q_+2] = (av.z > 0) ? ((x_ >= 1.f) ? x_ : y_) : 0.f;          \
                x_ = rowEs * etv.w; y_ = rowFs * ftv.w;                           \
                p_[4*q_+3] = (av.w > 0) ? ((x_ >= 1.f) ? x_ : y_) : 0.f;          \
                psum_ += (p_[4*q_+0] + p_[4*q_+1]) + (p_[4*q_+2] + p_[4*q_+3]);   \
            }                                                                     \
            uint4 u0_, u1_;                                                       \
            u0_.x = h2u(p_[0],  p_[1]);  u0_.y = h2u(p_[2],  p_[3]);              \
            u0_.z = h2u(p_[4],  p_[5]);  u0_.w = h2u(p_[6],  p_[7]);              \
            u1_.x = h2u(p_[8],  p_[9]);  u1_.y = h2u(p_[10], p_[11]);             \
            u1_.z = h2u(p_[12], p_[13]); u1_.w = h2u(p_[14], p_[15]);             \
            *(uint4*)&sPh[pb_][r][16 * h]     = u0_;                              \
            *(uint4*)&sPh[pb_][r][16 * h + 8] = u1_;                              \
            psum_ += __shfl_down_sync(0xffffffffu, psum_, 1);                     \
            if (h == 0) denreg += psum_;                                          \
        }

    // ---- prologue ----
    int4 a4[4];
    {
        STAGE_V(jbase, 0);
        #pragma unroll
        for (int q = 0; q < 4; ++q)
            a4[q] = *(const int4*)(adj + adjrow + jbase + 16 * h + 4 * q);
        BUILD_P(jbase, a4, 0);
        STAGE_V(jbase + KC, 1);
        #pragma unroll
        for (int q = 0; q < 4; ++q)
            a4[q] = *(const int4*)(adj + adjrow + jbase + KC + 16 * h + 4 * q);
        cp_wait0();
        __syncthreads();
    }

    for (int c = 0; c < NC; ++c) {
        const int buf = c & 1;
        const uint32_t bufOff = (uint32_t)buf * BUF_STRIDE;

        // ---- overlapped build of P(c+1) ----
        if (c + 1 < NC) {
            BUILD_P(jbase + (c + 1) * KC, a4, buf ^ 1);
            if (c + 2 < NC) {
                if (w == 0) {
                    const int jn = jbase + (c + 2) * KC + 16 * h;
                    pf_l1(g_Et + jn); pf_l1(g_Ft + jn);
                }
                #pragma unroll
                for (int q = 0; q < 4; ++q)
                    a4[q] = *(const int4*)(adj + adjrow + jbase + (c + 2) * KC + 16 * h + 4 * q);
            }
        }

        // ---- MMA phase: 2 ksteps of k=16, fragments via ldmatrix ----
        #pragma unroll
        for (int ks = 0; ks < 2; ++ks) {
            const uint32_t kOff = (uint32_t)(32 * ks);   // 16 halves
            uint32_t afrag[2][4];
            ldm_x4(afrag[0], aAddr[0] + bufOff + kOff);
            ldm_x4(afrag[1], aAddr[1] + bufOff + kOff);
            #pragma unroll
            for (int n = 0; n < 8; ++n) {
                uint32_t b0, b1;
                ldm_x2(b0, b1, bAddr + bufOff + kOff + (uint32_t)(n * 640));
                mma_f16_16x8x16(acc[0][n], afrag[0], b0, b1);
                mma_f16_16x8x16(acc[1][n], afrag[1], b0, b1);
            }
        }

        if (c + 1 < NC) {
            cp_wait0();
            __syncthreads();
            if (c + 2 < NC)
                STAGE_V(jbase + (c + 2) * KC, buf);
        }
    }

    // ---- epilogue ----
    float* outp = g_parts[jsp];
    #pragma unroll
    for (int m = 0; m < 2; ++m) {
        #pragma unroll
        for (int n = 0; n < 8; ++n) {
            const int row0 = rb + mrow + 16 * m + g;
            const int col  = ncol + 8 * n + 2 * t4;
            *(float2*)(outp + (size_t)row0 * DD + col) =
                make_float2(acc[m][n][0], acc[m][n][1]);
            *(float2*)(outp + (size_t)(row0 + 8) * DD + col) =
                make_float2(acc[m][n][2], acc[m][n][3]);
        }
    }
    __syncthreads();
    if (h == 0) sDen[r] = denreg;
    __syncthreads();
    if (tid < 128) g_dparts[jsp][rb + tid] = sDen[tid];
}

// ---------------- Kernel D: combine partials, normalize, relu ----------------
__global__ void k_final(float* __restrict__ out) {
    int idx = blockIdx.x * 256 + threadIdx.x;
    int r = idx >> 7;
    float dsum = g_dparts[0][r] + g_dparts[1][r] + g_dparts[2][r];
    float v = g_parts[0][idx] + g_parts[1][idx] + g_parts[2][idx];
    out[idx] = fmaxf(v / dsum, 0.f);
}

// ---------------- launch ----------------
extern "C" void kernel_launch(void* const* d_in, const int* in_sizes, int n_in,
                              void* d_out, int out_size) {
    const float* emb = (const float*)d_in[0];
    const int*   adj = (const int*)d_in[1];
    const float* W   = (const float*)d_in[2];
    const float* a   = (const float*)d_in[3];
    float* out = (float*)d_out;

    cudaFuncSetAttribute(k_mma, cudaFuncAttributeMaxDynamicSharedMemorySize, SMEM_BYTES);

    k_transW<<<(DD * DD + 255) / 256, 256>>>(W);
    k_enew<<<NN / 16, 256>>>(emb);
    k_scal<<<NN, 128>>>(a);
    k_vhT<<<dim3(NN / 32, DD / 32), dim3(32, 8)>>>();
    k_mma<<<dim3(MBLK, JSPLIT), 256, SMEM_BYTES>>>(adj);
    k_final<<<(NN * DD) / 256, 256>>>(out);
}

// round 15
// speedup vs baseline: 1.1409x; 1.1409x over previous
#include <cuda_runtime.h>
#include <cuda_fp16.h>
#include <cstdint>

#define NN 12288
#define DD 128
#define JSPLIT 3
#define JLEN (NN / JSPLIT)      // 4096
#define KC 32
#define NC (JLEN / KC)          // 128 chunks
#define MB 128
#define MBLK (NN / MB)          // 96

// dynamic smem layout (halves for tiles, floats for den)
#define SPH_BYTES  (2 * 128 * 40 * 2)     // 20480
#define SVH_BYTES  (2 * 128 * 40 * 2)     // 20480
#define SPH_OFF    0
#define SVH_OFF    SPH_BYTES
#define DEN_OFF    (SPH_BYTES + SVH_BYTES)
#define SMEM_BYTES (DEN_OFF + 128 * 4)    // 41472

// ---------------- static scratch ----------------
__device__ float  g_WT[DD * DD];
__device__ __half g_VhT[(size_t)DD * NN];          // fp16 V transposed: [dim][node]
__device__ float  g_s[NN], g_t[NN];
__device__ float  g_Es[NN], g_Et[NN], g_Fs[NN], g_Ft[NN];
__device__ float  g_parts[JSPLIT][(size_t)NN * DD];
__device__ float  g_dparts[JSPLIT][NN];

__device__ __forceinline__ void mma_f16_16x8x16(float* c, const uint32_t* a,
                                                uint32_t b0, uint32_t b1) {
    asm volatile(
        "mma.sync.aligned.m16n8k16.row.col.f32.f16.f16.f32 "
        "{%0,%1,%2,%3}, {%4,%5,%6,%7}, {%8,%9}, {%0,%1,%2,%3};"
        : "+f"(c[0]), "+f"(c[1]), "+f"(c[2]), "+f"(c[3])
        : "r"(a[0]), "r"(a[1]), "r"(a[2]), "r"(a[3]), "r"(b0), "r"(b1));
}
__device__ __forceinline__ void cp_async16(uint32_t dst, const void* src) {
    asm volatile("cp.async.ca.shared.global [%0], [%1], 16;"
                 :: "r"(dst), "l"(src) : "memory");
}
__device__ __forceinline__ void cp_commit() {
    asm volatile("cp.async.commit_group;" ::: "memory");
}
__device__ __forceinline__ void cp_wait0() {
    asm volatile("cp.async.wait_group 0;" ::: "memory");
}
__device__ __forceinline__ void pf_l1(const void* p) {
    asm volatile("prefetch.global.L1 [%0];" :: "l"(p));
}
__device__ __forceinline__ uint32_t h2u(float lo, float hi) {
    __half2 h = __float22half2_rn(make_float2(lo, hi));
    return *(uint32_t*)&h;
}

// ---------------- Kernel A0: transpose W ----------------
__global__ void k_transW(const float* __restrict__ W) {
    int i = blockIdx.x * 256 + threadIdx.x;
    if (i < DD * DD) {
        int d = i >> 7, k = i & 127;
        g_WT[k * DD + d] = W[i];
    }
}

// ---------------- Kernel A (fused): e_new GEMM + s/t scalars + fp16 V^T ----------------
// 16 rows per block. After the GEMM, the output tile lives in smem (eo) and is
// consumed in-place for: (1) s,t dot products + exp factors, (2) fp16 transposed
// writes to g_VhT. Replaces the old k_scal and k_vhT kernels; g_V is never
// materialized in gmem.
__global__ __launch_bounds__(256) void k_enew(const float* __restrict__ emb,
                                              const float* __restrict__ a) {
    const int rb = blockIdx.x * 16;
    const int tid = threadIdx.x;
    __shared__ float es[16][128];
    __shared__ float eo[16][128];

    for (int i = tid; i < 16 * 128; i += 256) {
        int r = i >> 7, k = i & 127;
        es[r][k] = emb[(size_t)(rb + r) * DD + k];
    }
    __syncthreads();

    const int rg = tid >> 5;
    const int dq = tid & 31;
    float acc[2][4];
    #pragma unroll
    for (int i = 0; i < 2; i++)
        #pragma unroll
        for (int j = 0; j < 4; j++) acc[i][j] = 0.f;
    #pragma unroll 4
    for (int k = 0; k < 128; ++k) {
        float4 wv = *(const float4*)&g_WT[k * DD + 4 * dq];
        float e0 = es[rg * 2 + 0][k];
        float e1 = es[rg * 2 + 1][k];
        acc[0][0] += e0 * wv.x; acc[0][1] += e0 * wv.y; acc[0][2] += e0 * wv.z; acc[0][3] += e0 * wv.w;
        acc[1][0] += e1 * wv.x; acc[1][1] += e1 * wv.y; acc[1][2] += e1 * wv.z; acc[1][3] += e1 * wv.w;
    }
    #pragma unroll
    for (int rr = 0; rr < 2; ++rr)
        *(float4*)&eo[rg * 2 + rr][4 * dq] = make_float4(acc[rr][0], acc[rr][1],
                                                         acc[rr][2], acc[rr][3]);
    __syncthreads();

    // ---- s, t scalars: warp w owns rows 2w, 2w+1 ----
    {
        const int wrp = tid >> 5, lane = tid & 31;
        #pragma unroll
        for (int rr = 0; rr < 2; ++rr) {
            const int row = 2 * wrp + rr;
            float sp = 0.f, tp = 0.f;
            #pragma unroll
            for (int q = 0; q < 4; ++q) {
                float v = eo[row][lane + 32 * q];
                sp += v * a[lane + 32 * q];
                tp += v * a[DD + lane + 32 * q];
            }
            #pragma unroll
            for (int off = 16; off; off >>= 1) {
                sp += __shfl_down_sync(0xffffffffu, sp, off);
                tp += __shfl_down_sync(0xffffffffu, tp, off);
            }
            if (lane == 0) {
                const int i = rb + row;
                g_s[i] = sp; g_Es[i] = expf(sp); g_Fs[i] = expf(0.01f * sp);
                g_t[i] = tp; g_Et[i] = expf(tp); g_Ft[i] = expf(0.01f * tp);
            }
        }
    }

    // ---- fp16 transposed write: thread (d, seg) -> g_VhT[d][rb + 8*seg .. +7] ----
    {
        const int d   = tid >> 1;
        const int seg = tid & 1;
        __half hbuf[8];
        #pragma unroll
        for (int j = 0; j < 8; ++j)
            hbuf[j] = __float2half(eo[8 * seg + j][d]);
        *(uint4*)&g_VhT[(size_t)d * NN + rb + 8 * seg] = *(uint4*)hbuf;
    }
}

// ---------------- Kernel C: pipelined fp16 mma.sync  P @ V  (R13 verbatim) ----------------
__global__ __launch_bounds__(256, 2) void k_mma(const int* __restrict__ adj) {
    extern __shared__ char smemc[];
    __half (*sPh)[128][40] = (__half (*)[128][40])(smemc + SPH_OFF);
    __half (*sVh)[128][40] = (__half (*)[128][40])(smemc + SVH_OFF);
    float* sDen            = (float*)(smemc + DEN_OFF);
    const uint32_t svh_base = (uint32_t)__cvta_generic_to_shared(smemc + SVH_OFF);

    const int tid = threadIdx.x;
    const int w   = tid >> 5;
    const int l   = tid & 31;
    const int g   = l >> 2;
    const int t4  = l & 3;
    const int rb  = blockIdx.x * MB;
    const int jsp = blockIdx.y;

    const int mrow = (w & 3) * 32;
    const int ncol = (w >> 2) * 64;

    const int r = tid >> 1;
    const int h = tid & 1;
    const float rowS  = g_s [rb + r];
    const float rowEs = g_Es[rb + r];
    const float rowFs = g_Fs[rb + r];
    const size_t adjrow = (size_t)(rb + r) * NN;

    float denreg = 0.f;

    float acc[2][8][4];
    #pragma unroll
    for (int m = 0; m < 2; m++)
        #pragma unroll
        for (int n = 0; n < 8; n++)
            #pragma unroll
            for (int i = 0; i < 4; i++) acc[m][n][i] = 0.f;

    const int jbase = jsp * JLEN;

    #define STAGE_V(jb_, buf_)                                                    \
        {                                                                         \
            _Pragma("unroll")                                                     \
            for (int it = 0; it < 2; ++it) {                                      \
                int f_ = tid + it * 256;                                          \
                int d_ = f_ >> 2, q_ = f_ & 3;                                    \
                uint32_t dst_ = svh_base +                                        \
                    (uint32_t)((((buf_) * 128 + d_) * 40 + 8 * q_) * 2);          \
                cp_async16(dst_, g_VhT + (size_t)d_ * NN + (jb_) + 8 * q_);       \
            }                                                                     \
            cp_commit();                                                          \
        }

    #define BUILD_P(jb_, A4_, pb_)                                                \
        {                                                                         \
            float p_[16];                                                         \
            float psum_ = 0.f;                                                    \
            _Pragma("unroll")                                                     \
            for (int q_ = 0; q_ < 4; ++q_) {                                      \
                const int j_ = (jb_) + 16 * h + 4 * q_;                           \
                int4   av  = A4_[q_];                                             \
                float4 tv  = *(const float4*)(g_t  + j_);                         \
                float4 etv = *(const float4*)(g_Et + j_);                         \
                float4 ftv = *(const float4*)(g_Ft + j_);                         \
                p_[4*q_+0] = (av.x > 0) ? ((rowS + tv.x >= 0.f) ? rowEs * etv.x : rowFs * ftv.x) : 0.f; \
                p_[4*q_+1] = (av.y > 0) ? ((rowS + tv.y >= 0.f) ? rowEs * etv.y : rowFs * ftv.y) : 0.f; \
                p_[4*q_+2] = (av.z > 0) ? ((rowS + tv.z >= 0.f) ? rowEs * etv.z : rowFs * ftv.z) : 0.f; \
                p_[4*q_+3] = (av.w > 0) ? ((rowS + tv.w >= 0.f) ? rowEs * etv.w : rowFs * ftv.w) : 0.f; \
                psum_ += (p_[4*q_+0] + p_[4*q_+1]) + (p_[4*q_+2] + p_[4*q_+3]);   \
            }                                                                     \
            uint4 u0_, u1_;                                                       \
            u0_.x = h2u(p_[0],  p_[1]);  u0_.y = h2u(p_[2],  p_[3]);              \
            u0_.z = h2u(p_[4],  p_[5]);  u0_.w = h2u(p_[6],  p_[7]);              \
            u1_.x = h2u(p_[8],  p_[9]);  u1_.y = h2u(p_[10], p_[11]);             \
            u1_.z = h2u(p_[12], p_[13]); u1_.w = h2u(p_[14], p_[15]);             \
            *(uint4*)&sPh[pb_][r][16 * h]     = u0_;                              \
            *(uint4*)&sPh[pb_][r][16 * h + 8] = u1_;                              \
            psum_ += __shfl_down_sync(0xffffffffu, psum_, 1);                     \
            if (h == 0) denreg += psum_;                                          \
        }

    // ---- prologue: chunks 0 and 1 ----
    int4 a4[4];
    {
        STAGE_V(jbase, 0);
        #pragma unroll
        for (int q = 0; q < 4; ++q)
            a4[q] = *(const int4*)(adj + adjrow + jbase + 16 * h + 4 * q);
        BUILD_P(jbase, a4, 0);
        STAGE_V(jbase + KC, 1);
        #pragma unroll
        for (int q = 0; q < 4; ++q)
            a4[q] = *(const int4*)(adj + adjrow + jbase + KC + 16 * h + 4 * q);
        cp_wait0();
        __syncthreads();
    }

    for (int c = 0; c < NC; ++c) {
        const int buf = c & 1;

        // ---- overlapped build of P(c+1) ----
        if (c + 1 < NC) {
            BUILD_P(jbase + (c + 1) * KC, a4, buf ^ 1);
            if (c + 2 < NC) {
                if (w == 0) {
                    const int jn = jbase + (c + 2) * KC + 16 * h;
                    pf_l1(g_t + jn); pf_l1(g_Et + jn); pf_l1(g_Ft + jn);
                }
                #pragma unroll
                for (int q = 0; q < 4; ++q)
                    a4[q] = *(const int4*)(adj + adjrow + jbase + (c + 2) * KC + 16 * h + 4 * q);
            }
        }

        // ---- MMA phase on chunk c: 2 ksteps of k=16 ----
        #pragma unroll
        for (int ks = 0; ks < 2; ++ks) {
            const int k0 = 16 * ks;
            uint32_t afrag[2][4];
            #pragma unroll
            for (int m = 0; m < 2; ++m) {
                const int r0 = mrow + 16 * m;
                afrag[m][0] = *(const uint32_t*)&sPh[buf][r0 + g    ][k0 + 2 * t4    ];
                afrag[m][1] = *(const uint32_t*)&sPh[buf][r0 + g + 8][k0 + 2 * t4    ];
                afrag[m][2] = *(const uint32_t*)&sPh[buf][r0 + g    ][k0 + 2 * t4 + 8];
                afrag[m][3] = *(const uint32_t*)&sPh[buf][r0 + g + 8][k0 + 2 * t4 + 8];
            }
            #pragma unroll
            for (int n = 0; n < 8; ++n) {
                const int n0 = ncol + 8 * n;
                uint32_t b0 = *(const uint32_t*)&sVh[buf][n0 + g][k0 + 2 * t4    ];
                uint32_t b1 = *(const uint32_t*)&sVh[buf][n0 + g][k0 + 2 * t4 + 8];
                mma_f16_16x8x16(acc[0][n], afrag[0], b0, b1);
                mma_f16_16x8x16(acc[1][n], afrag[1], b0, b1);
            }
        }

        if (c + 1 < NC) {
            cp_wait0();
            __syncthreads();
            if (c + 2 < NC)
                STAGE_V(jbase + (c + 2) * KC, buf);
        }
    }

    // ---- epilogue ----
    float* outp = g_parts[jsp];
    #pragma unroll
    for (int m = 0; m < 2; ++m) {
        #pragma unroll
        for (int n = 0; n < 8; ++n) {
            const int row0 = rb + mrow + 16 * m + g;
            const int col  = ncol + 8 * n + 2 * t4;
            *(float2*)(outp + (size_t)row0 * DD + col) =
                make_float2(acc[m][n][0], acc[m][n][1]);
            *(float2*)(outp + (size_t)(row0 + 8) * DD + col) =
                make_float2(acc[m][n][2], acc[m][n][3]);
        }
    }
    __syncthreads();
    if (h == 0) sDen[r] = denreg;
    __syncthreads();
    if (tid < 128) g_dparts[jsp][rb + tid] = sDen[tid];
}

// ---------------- Kernel D: combine partials, normalize, relu ----------------
__global__ void k_final(float* __restrict__ out) {
    int idx = blockIdx.x * 256 + threadIdx.x;
    int r = idx >> 7;
    float dsum = g_dparts[0][r] + g_dparts[1][r] + g_dparts[2][r];
    float v = g_parts[0][idx] + g_parts[1][idx] + g_parts[2][idx];
    out[idx] = fmaxf(v / dsum, 0.f);
}

// ---------------- launch ----------------
extern "C" void kernel_launch(void* const* d_in, const int* in_sizes, int n_in,
                              void* d_out, int out_size) {
    const float* emb = (const float*)d_in[0];
    const int*   adj = (const int*)d_in[1];
    const float* W   = (const float*)d_in[2];
    const float* a   = (const float*)d_in[3];
    float* out = (float*)d_out;

    cudaFuncSetAttribute(k_mma, cudaFuncAttributeMaxDynamicSharedMemorySize, SMEM_BYTES);

    k_transW<<<(DD * DD + 255) / 256, 256>>>(W);
    k_enew<<<NN / 16, 256>>>(emb, a);
    k_mma<<<dim3(MBLK, JSPLIT), 256, SMEM_BYTES>>>(adj);
    k_final<<<(NN * DD) / 256, 256>>>(out);
}

// round 16
// speedup vs baseline: 1.1602x; 1.0169x over previous
#include <cuda_runtime.h>
#include <cuda_fp16.h>
#include <cstdint>

#define NN 12288
#define DD 128
#define JSPLIT 3
#define JLEN (NN / JSPLIT)      // 4096
#define KC 32
#define NC (JLEN / KC)          // 128 chunks
#define MB 128
#define MBLK (NN / MB)          // 96

// dynamic smem layout (halves for tiles, floats for den)
#define SPH_BYTES  (2 * 128 * 40 * 2)     // 20480
#define SVH_BYTES  (2 * 128 * 40 * 2)     // 20480
#define SPH_OFF    0
#define SVH_OFF    SPH_BYTES
#define DEN_OFF    (SPH_BYTES + SVH_BYTES)
#define SMEM_BYTES (DEN_OFF + 128 * 4)    // 41472

// ---------------- static scratch ----------------
__device__ float  g_WT[DD * DD];
__device__ __half g_VhT[(size_t)DD * NN];          // fp16 V transposed: [dim][node]
__device__ float  g_s[NN], g_t[NN];
__device__ float  g_Es[NN], g_Et[NN], g_Fs[NN], g_Ft[NN];
__device__ float  g_parts[JSPLIT][(size_t)NN * DD];
__device__ float  g_dparts[JSPLIT][NN];

__device__ __forceinline__ void mma_f16_16x8x16(float* c, const uint32_t* a,
                                                uint32_t b0, uint32_t b1) {
    asm volatile(
        "mma.sync.aligned.m16n8k16.row.col.f32.f16.f16.f32 "
        "{%0,%1,%2,%3}, {%4,%5,%6,%7}, {%8,%9}, {%0,%1,%2,%3};"
        : "+f"(c[0]), "+f"(c[1]), "+f"(c[2]), "+f"(c[3])
        : "r"(a[0]), "r"(a[1]), "r"(a[2]), "r"(a[3]), "r"(b0), "r"(b1));
}
__device__ __forceinline__ void cp_async16(uint32_t dst, const void* src) {
    asm volatile("cp.async.ca.shared.global [%0], [%1], 16;"
                 :: "r"(dst), "l"(src) : "memory");
}
__device__ __forceinline__ void cp_commit() {
    asm volatile("cp.async.commit_group;" ::: "memory");
}
__device__ __forceinline__ void cp_wait0() {
    asm volatile("cp.async.wait_group 0;" ::: "memory");
}
__device__ __forceinline__ void pf_l1(const void* p) {
    asm volatile("prefetch.global.L1 [%0];" :: "l"(p));
}
__device__ __forceinline__ uint32_t h2u(float lo, float hi) {
    __half2 h = __float22half2_rn(make_float2(lo, hi));
    return *(uint32_t*)&h;
}

// ---------------- Kernel A0: transpose W ----------------
__global__ void k_transW(const float* __restrict__ W) {
    int i = blockIdx.x * 256 + threadIdx.x;
    if (i < DD * DD) {
        int d = i >> 7, k = i & 127;
        g_WT[k * DD + d] = W[i];
    }
}

// ---------------- Kernel A (fused, 64-row tiles): GEMM + s/t + fp16 V^T ----------------
// 64 rows per block, 256 threads. One aliased smem buffer: emb tile (es) during
// the GEMM, then the output tile (eo) after a barrier. g_VhT writes are 64B
// contiguous per thread (full sectors).
__global__ __launch_bounds__(256) void k_enew(const float* __restrict__ emb,
                                              const float* __restrict__ a) {
    const int rb = blockIdx.x * 64;
    const int tid = threadIdx.x;
    __shared__ float eb[64][132];       // es, then eo (aliased)
    __shared__ float sa[2 * DD];

    sa[tid] = a[tid];                   // 256 == 2*DD

    // load emb tile: 2048 float4, 8 per thread
    #pragma unroll
    for (int it = 0; it < 8; ++it) {
        int f = tid + it * 256;
        int r = f >> 5, q = f & 31;
        *(float4*)&eb[r][4 * q] = *(const float4*)&emb[(size_t)(rb + r) * DD + 4 * q];
    }
    __syncthreads();

    // GEMM: group rg owns rows 8rg..8rg+7; dq owns dims 4dq..4dq+3
    const int rg = tid >> 5;
    const int dq = tid & 31;
    float acc[8][4];
    #pragma unroll
    for (int i = 0; i < 8; i++)
        #pragma unroll
        for (int j = 0; j < 4; j++) acc[i][j] = 0.f;
    for (int k = 0; k < 128; ++k) {
        float4 wv = *(const float4*)&g_WT[k * DD + 4 * dq];
        #pragma unroll
        for (int rr = 0; rr < 8; ++rr) {
            float e = eb[rg * 8 + rr][k];
            acc[rr][0] += e * wv.x; acc[rr][1] += e * wv.y;
            acc[rr][2] += e * wv.z; acc[rr][3] += e * wv.w;
        }
    }
    __syncthreads();                    // all es reads done; buffer becomes eo
    #pragma unroll
    for (int rr = 0; rr < 8; ++rr)
        *(float4*)&eb[rg * 8 + rr][4 * dq] =
            make_float4(acc[rr][0], acc[rr][1], acc[rr][2], acc[rr][3]);
    __syncthreads();

    // ---- s, t scalars: warp wrp owns rows 8wrp..8wrp+7 ----
    {
        const int wrp = tid >> 5, lane = tid & 31;
        #pragma unroll
        for (int rr = 0; rr < 8; ++rr) {
            const int row = 8 * wrp + rr;
            float sp = 0.f, tp = 0.f;
            #pragma unroll
            for (int q = 0; q < 4; ++q) {
                float v = eb[row][lane + 32 * q];
                sp += v * sa[lane + 32 * q];
                tp += v * sa[DD + lane + 32 * q];
            }
            #pragma unroll
            for (int off = 16; off; off >>= 1) {
                sp += __shfl_down_sync(0xffffffffu, sp, off);
                tp += __shfl_down_sync(0xffffffffu, tp, off);
            }
            if (lane == 0) {
                const int i = rb + row;
                g_s[i] = sp; g_Es[i] = expf(sp); g_Fs[i] = expf(0.01f * sp);
                g_t[i] = tp; g_Et[i] = expf(tp); g_Ft[i] = expf(0.01f * tp);
            }
        }
    }

    // ---- fp16 transposed write: thread (d, half) -> g_VhT[d][rb+32*half .. +31] ----
    {
        const int d    = tid & 127;
        const int half = tid >> 7;
        uint4 hbu[4];
        __half* hp = (__half*)hbu;
        #pragma unroll
        for (int i = 0; i < 32; ++i)
            hp[i] = __float2half(eb[32 * half + i][d]);   // bank = 4*row+d: conflict-free
        __half* dst = g_VhT + (size_t)d * NN + rb + 32 * half;
        #pragma unroll
        for (int m = 0; m < 4; ++m)
            *(uint4*)(dst + 8 * m) = hbu[m];              // 64B contiguous per thread
    }
}

// ---------------- Kernel C: pipelined fp16 mma.sync  P @ V  (R13 verbatim) ----------------
__global__ __launch_bounds__(256, 2) void k_mma(const int* __restrict__ adj) {
    extern __shared__ char smemc[];
    __half (*sPh)[128][40] = (__half (*)[128][40])(smemc + SPH_OFF);
    __half (*sVh)[128][40] = (__half (*)[128][40])(smemc + SVH_OFF);
    float* sDen            = (float*)(smemc + DEN_OFF);
    const uint32_t svh_base = (uint32_t)__cvta_generic_to_shared(smemc + SVH_OFF);

    const int tid = threadIdx.x;
    const int w   = tid >> 5;
    const int l   = tid & 31;
    const int g   = l >> 2;
    const int t4  = l & 3;
    const int rb  = blockIdx.x * MB;
    const int jsp = blockIdx.y;

    const int mrow = (w & 3) * 32;
    const int ncol = (w >> 2) * 64;

    const int r = tid >> 1;
    const int h = tid & 1;
    const float rowS  = g_s [rb + r];
    const float rowEs = g_Es[rb + r];
    const float rowFs = g_Fs[rb + r];
    const size_t adjrow = (size_t)(rb + r) * NN;

    float denreg = 0.f;

    float acc[2][8][4];
    #pragma unroll
    for (int m = 0; m < 2; m++)
        #pragma unroll
        for (int n = 0; n < 8; n++)
            #pragma unroll
            for (int i = 0; i < 4; i++) acc[m][n][i] = 0.f;

    const int jbase = jsp * JLEN;

    #define STAGE_V(jb_, buf_)                                                    \
        {                                                                         \
            _Pragma("unroll")                                                     \
            for (int it = 0; it < 2; ++it) {                                      \
                int f_ = tid + it * 256;                                          \
                int d_ = f_ >> 2, q_ = f_ & 3;                                    \
                uint32_t dst_ = svh_base +                                        \
                    (uint32_t)((((buf_) * 128 + d_) * 40 + 8 * q_) * 2);          \
                cp_async16(dst_, g_VhT + (size_t)d_ * NN + (jb_) + 8 * q_);       \
            }                                                                     \
            cp_commit();                                                          \
        }

    #define BUILD_P(jb_, A4_, pb_)                                                \
        {                                                                         \
            float p_[16];                                                         \
            float psum_ = 0.f;                                                    \
            _Pragma("unroll")                                                     \
            for (int q_ = 0; q_ < 4; ++q_) {                                      \
                const int j_ = (jb_) + 16 * h + 4 * q_;                           \
                int4   av  = A4_[q_];                                             \
                float4 tv  = *(const float4*)(g_t  + j_);                         \
                float4 etv = *(const float4*)(g_Et + j_);                         \
                float4 ftv = *(const float4*)(g_Ft + j_);                         \
                p_[4*q_+0] = (av.x > 0) ? ((rowS + tv.x >= 0.f) ? rowEs * etv.x : rowFs * ftv.x) : 0.f; \
                p_[4*q_+1] = (av.y > 0) ? ((rowS + tv.y >= 0.f) ? rowEs * etv.y : rowFs * ftv.y) : 0.f; \
                p_[4*q_+2] = (av.z > 0) ? ((rowS + tv.z >= 0.f) ? rowEs * etv.z : rowFs * ftv.z) : 0.f; \
                p_[4*q_+3] = (av.w > 0) ? ((rowS + tv.w >= 0.f) ? rowEs * etv.w : rowFs * ftv.w) : 0.f; \
                psum_ += (p_[4*q_+0] + p_[4*q_+1]) + (p_[4*q_+2] + p_[4*q_+3]);   \
            }                                                                     \
            uint4 u0_, u1_;                                                       \
            u0_.x = h2u(p_[0],  p_[1]);  u0_.y = h2u(p_[2],  p_[3]);              \
            u0_.z = h2u(p_[4],  p_[5]);  u0_.w = h2u(p_[6],  p_[7]);              \
            u1_.x = h2u(p_[8],  p_[9]);  u1_.y = h2u(p_[10], p_[11]);             \
            u1_.z = h2u(p_[12], p_[13]); u1_.w = h2u(p_[14], p_[15]);             \
            *(uint4*)&sPh[pb_][r][16 * h]     = u0_;                              \
            *(uint4*)&sPh[pb_][r][16 * h + 8] = u1_;                              \
            psum_ += __shfl_down_sync(0xffffffffu, psum_, 1);                     \
            if (h == 0) denreg += psum_;                                          \
        }

    // ---- prologue: chunks 0 and 1 ----
    int4 a4[4];
    {
        STAGE_V(jbase, 0);
        #pragma unroll
        for (int q = 0; q < 4; ++q)
            a4[q] = *(const int4*)(adj + adjrow + jbase + 16 * h + 4 * q);
        BUILD_P(jbase, a4, 0);
        STAGE_V(jbase + KC, 1);
        #pragma unroll
        for (int q = 0; q < 4; ++q)
            a4[q] = *(const int4*)(adj + adjrow + jbase + KC + 16 * h + 4 * q);
        cp_wait0();
        __syncthreads();
    }

    for (int c = 0; c < NC; ++c) {
        const int buf = c & 1;

        // ---- overlapped build of P(c+1) ----
        if (c + 1 < NC) {
            BUILD_P(jbase + (c + 1) * KC, a4, buf ^ 1);
            if (c + 2 < NC) {
                if (w == 0) {
                    const int jn = jbase + (c + 2) * KC + 16 * h;
                    pf_l1(g_t + jn); pf_l1(g_Et + jn); pf_l1(g_Ft + jn);
                }
                #pragma unroll
                for (int q = 0; q < 4; ++q)
                    a4[q] = *(const int4*)(adj + adjrow + jbase + (c + 2) * KC + 16 * h + 4 * q);
            }
        }

        // ---- MMA phase on chunk c: 2 ksteps of k=16 ----
        #pragma unroll
        for (int ks = 0; ks < 2; ++ks) {
            const int k0 = 16 * ks;
            uint32_t afrag[2][4];
            #pragma unroll
            for (int m = 0; m < 2; ++m) {
                const int r0 = mrow + 16 * m;
                afrag[m][0] = *(const uint32_t*)&sPh[buf][r0 + g    ][k0 + 2 * t4    ];
                afrag[m][1] = *(const uint32_t*)&sPh[buf][r0 + g + 8][k0 + 2 * t4    ];
                afrag[m][2] = *(const uint32_t*)&sPh[buf][r0 + g    ][k0 + 2 * t4 + 8];
                afrag[m][3] = *(const uint32_t*)&sPh[buf][r0 + g + 8][k0 + 2 * t4 + 8];
            }
            #pragma unroll
            for (int n = 0; n < 8; ++n) {
                const int n0 = ncol + 8 * n;
                uint32_t b0 = *(const uint32_t*)&sVh[buf][n0 + g][k0 + 2 * t4    ];
                uint32_t b1 = *(const uint32_t*)&sVh[buf][n0 + g][k0 + 2 * t4 + 8];
                mma_f16_16x8x16(acc[0][n], afrag[0], b0, b1);
                mma_f16_16x8x16(acc[1][n], afrag[1], b0, b1);
            }
        }

        if (c + 1 < NC) {
            cp_wait0();
            __syncthreads();
            if (c + 2 < NC)
                STAGE_V(jbase + (c + 2) * KC, buf);
        }
    }

    // ---- epilogue ----
    float* outp = g_parts[jsp];
    #pragma unroll
    for (int m = 0; m < 2; ++m) {
        #pragma unroll
        for (int n = 0; n < 8; ++n) {
            const int row0 = rb + mrow + 16 * m + g;
            const int col  = ncol + 8 * n + 2 * t4;
            *(float2*)(outp + (size_t)row0 * DD + col) =
                make_float2(acc[m][n][0], acc[m][n][1]);
            *(float2*)(outp + (size_t)(row0 + 8) * DD + col) =
                make_float2(acc[m][n][2], acc[m][n][3]);
        }
    }
    __syncthreads();
    if (h == 0) sDen[r] = denreg;
    __syncthreads();
    if (tid < 128) g_dparts[jsp][rb + tid] = sDen[tid];
}

// ---------------- Kernel D: combine partials, normalize, relu (float4) ----------------
__global__ void k_final(float* __restrict__ out) {
    int i4 = blockIdx.x * 256 + threadIdx.x;     // float4 index; all 4 elems same row
    int r  = i4 >> 5;                            // (i4*4) >> 7
    float inv = 1.0f / (g_dparts[0][r] + g_dparts[1][r] + g_dparts[2][r]);
    float4 v0 = ((const float4*)g_parts[0])[i4];
    float4 v1 = ((const float4*)g_parts[1])[i4];
    float4 v2 = ((const float4*)g_parts[2])[i4];
    float4 o;
    o.x = fmaxf((v0.x + v1.x + v2.x) * inv, 0.f);
    o.y = fmaxf((v0.y + v1.y + v2.y) * inv, 0.f);
    o.z = fmaxf((v0.z + v1.z + v2.z) * inv, 0.f);
    o.w = fmaxf((v0.w + v1.w + v2.w) * inv, 0.f);
    ((float4*)out)[i4] = o;
}

// ---------------- launch ----------------
extern "C" void kernel_launch(void* const* d_in, const int* in_sizes, int n_in,
                              void* d_out, int out_size) {
    const float* emb = (const float*)d_in[0];
    const int*   adj = (const int*)d_in[1];
    const float* W   = (const float*)d_in[2];
    const float* a   = (const float*)d_in[3];
    float* out = (float*)d_out;

    cudaFuncSetAttribute(k_mma, cudaFuncAttributeMaxDynamicSharedMemorySize, SMEM_BYTES);

    k_transW<<<(DD * DD + 255) / 256, 256>>>(W);
    k_enew<<<NN / 64, 256>>>(emb, a);
    k_mma<<<dim3(MBLK, JSPLIT), 256, SMEM_BYTES>>>(adj);
    k_final<<<(NN * DD) / 1024, 256>>>(out);
}